// round 3
// baseline (speedup 1.0000x reference)
#include <cuda_runtime.h>
#include <cuda_bf16.h>
#include <cstdint>

#define NN 20000
#define EE 320000
#define CC 128
#define BB 20
#define RCUT 5.0f
#define EPSN 1e-8f
#define PI_F 3.14159265358979323846f

// ---------------- scratch (static device globals; no allocation) -------------
__device__ float g_x[NN * 384];     // x = silu(q@W1+b1)@W2+b2, [N,384]
__device__ float g_dq[NN * 128];    // scatter accum dq
__device__ float g_dmu[NN * 384];   // scatter accum dmu [N,3,128]

__device__ __forceinline__ float silu_f(float v) {
    return v / (1.0f + __expf(-v));
}

__device__ __forceinline__ void red_add_v4(float* ptr, float4 v) {
    asm volatile("red.global.add.v4.f32 [%0], {%1, %2, %3, %4};"
                 :: "l"(ptr), "f"(v.x), "f"(v.y), "f"(v.z), "f"(v.w)
                 : "memory");
}

// ============================================================================
// K1: per-node context MLP  x = silu(q@W1+b1)@W2+b2   (+ zero dq/dmu accums)
// block = 128 threads, 8 nodes per block, grid = N/8 = 2500
// ============================================================================
__global__ __launch_bounds__(128) void k_node_mlp(
    const float* __restrict__ q,
    const float* __restrict__ W1, const float* __restrict__ b1,
    const float* __restrict__ W2, const float* __restrict__ b2)
{
    __shared__ float sT[128 * 8];   // transposed activations [k][n]
    const int t = threadIdx.x;
    const int n0 = blockIdx.x * 8;

    // zero the scatter accumulators for this node range (done before K2 runs)
#pragma unroll
    for (int n = 0; n < 8; n++) {
        g_dq[(n0 + n) * 128 + t] = 0.0f;
        g_dmu[(n0 + n) * 384 + t] = 0.0f;
        g_dmu[(n0 + n) * 384 + 128 + t] = 0.0f;
        g_dmu[(n0 + n) * 384 + 256 + t] = 0.0f;
    }

    // stage qT: sT[k=t][n]
#pragma unroll
    for (int n = 0; n < 8; n++) sT[t * 8 + n] = q[(n0 + n) * 128 + t];
    __syncthreads();

    // h[n][t] = silu(b1[t] + sum_k q[n][k] * W1[k][t])
    float acc[8];
    {
        const float bb = __ldg(&b1[t]);
#pragma unroll
        for (int n = 0; n < 8; n++) acc[n] = bb;
    }
#pragma unroll 4
    for (int k = 0; k < 128; k++) {
        const float w = __ldg(&W1[k * 128 + t]);
        const float4* r = (const float4*)&sT[k * 8];
        const float4 a0 = r[0], a1 = r[1];
        acc[0] += a0.x * w; acc[1] += a0.y * w; acc[2] += a0.z * w; acc[3] += a0.w * w;
        acc[4] += a1.x * w; acc[5] += a1.y * w; acc[6] += a1.z * w; acc[7] += a1.w * w;
    }
    __syncthreads();
#pragma unroll
    for (int n = 0; n < 8; n++) sT[t * 8 + n] = silu_f(acc[n]);
    __syncthreads();

    // x[n][m] for m in {t, t+128, t+256}
    float y0[8], y1[8], y2[8];
    {
        const float c0 = __ldg(&b2[t]);
        const float c1 = __ldg(&b2[128 + t]);
        const float c2 = __ldg(&b2[256 + t]);
#pragma unroll
        for (int n = 0; n < 8; n++) { y0[n] = c0; y1[n] = c1; y2[n] = c2; }
    }
#pragma unroll 2
    for (int k = 0; k < 128; k++) {
        const float w0 = __ldg(&W2[k * 384 + t]);
        const float w1 = __ldg(&W2[k * 384 + 128 + t]);
        const float w2 = __ldg(&W2[k * 384 + 256 + t]);
        const float4* r = (const float4*)&sT[k * 8];
        const float4 h0 = r[0], h1 = r[1];
        y0[0] += h0.x * w0; y0[1] += h0.y * w0; y0[2] += h0.z * w0; y0[3] += h0.w * w0;
        y0[4] += h1.x * w0; y0[5] += h1.y * w0; y0[6] += h1.z * w0; y0[7] += h1.w * w0;
        y1[0] += h0.x * w1; y1[1] += h0.y * w1; y1[2] += h0.z * w1; y1[3] += h0.w * w1;
        y1[4] += h1.x * w1; y1[5] += h1.y * w1; y1[6] += h1.z * w1; y1[7] += h1.w * w1;
        y2[0] += h0.x * w2; y2[1] += h0.y * w2; y2[2] += h0.z * w2; y2[3] += h0.w * w2;
        y2[4] += h1.x * w2; y2[5] += h1.y * w2; y2[6] += h1.z * w2; y2[7] += h1.w * w2;
    }
#pragma unroll
    for (int n = 0; n < 8; n++) {
        g_x[(n0 + n) * 384 + t]       = y0[n];
        g_x[(n0 + n) * 384 + 128 + t] = y1[n];
        g_x[(n0 + n) * 384 + 256 + t] = y2[n];
    }
}

// ============================================================================
// K2: edge message kernel. warp per edge (16 edges/warp), 256 thr/block.
// Wij = (attrs @ W_filter + b_filter) * fcut ; gather x[j], mu[j];
// scatter dq/dmu via red.global.add.v4.f32.
// grid = E / (8*16) = 2500
// ============================================================================
#define EPW 16
__global__ __launch_bounds__(256) void k_edge(
    const int*   __restrict__ eidx,     // [2,E]
    const float* __restrict__ ew,       // [E]
    const float* __restrict__ evers,    // [E,3]
    const float* __restrict__ eattr,    // [E,B]
    const float* __restrict__ Wf,       // [B,384]
    const float* __restrict__ bf,       // [384]
    const float* __restrict__ mu)       // [N,3,128]
{
    __shared__ float sWf[BB * 384];
    __shared__ float sBf[384];
    for (int i = threadIdx.x; i < BB * 384; i += 256) sWf[i] = Wf[i];
    for (int i = threadIdx.x; i < 384; i += 256) sBf[i] = bf[i];
    __syncthreads();

    const int warp = threadIdx.x >> 5;
    const int lane = threadIdx.x & 31;
    const int c0 = lane * 4;
    const int ebase = (blockIdx.x * 8 + warp) * EPW;

    const float4 bf0 = *(const float4*)&sBf[c0];
    const float4 bf1 = *(const float4*)&sBf[128 + c0];
    const float4 bf2 = *(const float4*)&sBf[256 + c0];

    for (int it = 0; it < EPW; it++) {
        const int e = ebase + it;
        const int i = eidx[e];
        const int j = eidx[EE + e];
        const float wgt = __ldg(&ew[e]);
        const float fcut = (wgt < RCUT)
            ? 0.5f * (cosf((PI_F / RCUT) * wgt) + 1.0f) : 0.0f;
        const float a = (lane < BB) ? __ldg(&eattr[e * BB + lane]) : 0.0f;
        const float vx = __ldg(&evers[e * 3 + 0]);
        const float vy = __ldg(&evers[e * 3 + 1]);
        const float vz = __ldg(&evers[e * 3 + 2]);

        float4 w0 = bf0, w1 = bf1, w2 = bf2;
#pragma unroll
        for (int b = 0; b < BB; b++) {
            const float ab = __shfl_sync(0xffffffffu, a, b);
            const float4 f0 = *(const float4*)&sWf[b * 384 + c0];
            const float4 f1 = *(const float4*)&sWf[b * 384 + 128 + c0];
            const float4 f2 = *(const float4*)&sWf[b * 384 + 256 + c0];
            w0.x += ab * f0.x; w0.y += ab * f0.y; w0.z += ab * f0.z; w0.w += ab * f0.w;
            w1.x += ab * f1.x; w1.y += ab * f1.y; w1.z += ab * f1.z; w1.w += ab * f1.w;
            w2.x += ab * f2.x; w2.y += ab * f2.y; w2.z += ab * f2.z; w2.w += ab * f2.w;
        }
        w0.x *= fcut; w0.y *= fcut; w0.z *= fcut; w0.w *= fcut;
        w1.x *= fcut; w1.y *= fcut; w1.z *= fcut; w1.w *= fcut;
        w2.x *= fcut; w2.y *= fcut; w2.z *= fcut; w2.w *= fcut;

        const float4 x0 = __ldg((const float4*)&g_x[j * 384 + c0]);
        const float4 x1 = __ldg((const float4*)&g_x[j * 384 + 128 + c0]);
        const float4 x2 = __ldg((const float4*)&g_x[j * 384 + 256 + c0]);

        float4 dq, dR, dM;
        dq.x = x0.x * w0.x; dq.y = x0.y * w0.y; dq.z = x0.z * w0.z; dq.w = x0.w * w0.w;
        dR.x = x1.x * w1.x; dR.y = x1.y * w1.y; dR.z = x1.z * w1.z; dR.w = x1.w * w1.w;
        dM.x = x2.x * w2.x; dM.y = x2.y * w2.y; dM.z = x2.z * w2.z; dM.w = x2.w * w2.w;

        const float4 m0 = __ldg((const float4*)&mu[j * 384 + c0]);
        const float4 m1 = __ldg((const float4*)&mu[j * 384 + 128 + c0]);
        const float4 m2 = __ldg((const float4*)&mu[j * 384 + 256 + c0]);

        float4 d0, d1, d2;
        d0.x = dR.x * vx + dM.x * m0.x; d0.y = dR.y * vx + dM.y * m0.y;
        d0.z = dR.z * vx + dM.z * m0.z; d0.w = dR.w * vx + dM.w * m0.w;
        d1.x = dR.x * vy + dM.x * m1.x; d1.y = dR.y * vy + dM.y * m1.y;
        d1.z = dR.z * vy + dM.z * m1.z; d1.w = dR.w * vy + dM.w * m1.w;
        d2.x = dR.x * vz + dM.x * m2.x; d2.y = dR.y * vz + dM.y * m2.y;
        d2.z = dR.z * vz + dM.z * m2.z; d2.w = dR.w * vz + dM.w * m2.w;

        red_add_v4(&g_dq[i * 128 + c0], dq);
        red_add_v4(&g_dmu[i * 384 + c0], d0);
        red_add_v4(&g_dmu[i * 384 + 128 + c0], d1);
        red_add_v4(&g_dmu[i * 384 + 256 + c0], d2);
    }
}

// ============================================================================
// K3: PaiNN mixing. block = 128 threads, 8 nodes per block, grid = 2500.
// ============================================================================
__global__ __launch_bounds__(128) void k_mix(
    const float* __restrict__ q,
    const float* __restrict__ mu,
    const float* __restrict__ Wmix,   // [128,256]
    const float* __restrict__ Wm1,    // [256,128]
    const float* __restrict__ bm1,    // [128]
    const float* __restrict__ Wm2,    // [128,384]
    const float* __restrict__ bm2,    // [384]
    float* __restrict__ out_q,        // [N,128]
    float* __restrict__ out_mu)       // [N,3,128]
{
    __shared__ float sMuT[128 * 24];   // [k][v*8+n]
    __shared__ float sCtx[256 * 8];    // [k][n]
    __shared__ float sH2[128 * 8];     // [k][n]
    const int t = threadIdx.x;
    const int n0 = blockIdx.x * 8;

    // mun = mu + dmu (kept in regs AND staged transposed in smem); qn = q + dq
    float munr[24];
    float qn[8];
#pragma unroll
    for (int v = 0; v < 3; v++)
#pragma unroll
        for (int n = 0; n < 8; n++) {
            const int gi = (n0 + n) * 384 + v * 128 + t;
            const float m = mu[gi] + g_dmu[gi];
            munr[v * 8 + n] = m;
            sMuT[t * 24 + v * 8 + n] = m;
        }
#pragma unroll
    for (int n = 0; n < 8; n++)
        qn[n] = q[(n0 + n) * 128 + t] + g_dq[(n0 + n) * 128 + t];
    __syncthreads();

    // mu_V[n][v][t] = sum_k mun[n][v][k] * Wmix[k][t]
    float accV[24];
#pragma unroll
    for (int u = 0; u < 24; u++) accV[u] = 0.0f;
#pragma unroll 2
    for (int k = 0; k < 128; k++) {
        const float w = __ldg(&Wmix[k * 256 + t]);
        const float4* r = (const float4*)&sMuT[k * 24];
#pragma unroll
        for (int u = 0; u < 6; u++) {
            const float4 m = r[u];
            accV[4 * u + 0] += m.x * w;
            accV[4 * u + 1] += m.y * w;
            accV[4 * u + 2] += m.z * w;
            accV[4 * u + 3] += m.w * w;
        }
    }
    float Vn[8];
#pragma unroll
    for (int n = 0; n < 8; n++)
        Vn[n] = sqrtf(accV[n] * accV[n] + accV[8 + n] * accV[8 + n]
                      + accV[16 + n] * accV[16 + n] + EPSN);

    // mu_W[n][v][t] = sum_k mun[n][v][k] * Wmix[k][128+t]
    float accW[24];
#pragma unroll
    for (int u = 0; u < 24; u++) accW[u] = 0.0f;
#pragma unroll 2
    for (int k = 0; k < 128; k++) {
        const float w = __ldg(&Wmix[k * 256 + 128 + t]);
        const float4* r = (const float4*)&sMuT[k * 24];
#pragma unroll
        for (int u = 0; u < 6; u++) {
            const float4 m = r[u];
            accW[4 * u + 0] += m.x * w;
            accW[4 * u + 1] += m.y * w;
            accW[4 * u + 2] += m.z * w;
            accW[4 * u + 3] += m.w * w;
        }
    }
    float sdot[8];
#pragma unroll
    for (int n = 0; n < 8; n++)
        sdot[n] = accV[n] * accW[n] + accV[8 + n] * accW[8 + n]
                + accV[16 + n] * accW[16 + n];

    // ctx = [qn, Vn] transposed into smem
#pragma unroll
    for (int n = 0; n < 8; n++) {
        sCtx[t * 8 + n] = qn[n];
        sCtx[(128 + t) * 8 + n] = Vn[n];
    }
    __syncthreads();

    // h2[n][t] = silu(bm1[t] + sum_{k<256} ctx[n][k] * Wm1[k][t])
    float h2[8];
    {
        const float bb = __ldg(&bm1[t]);
#pragma unroll
        for (int n = 0; n < 8; n++) h2[n] = bb;
    }
#pragma unroll 4
    for (int k = 0; k < 256; k++) {
        const float w = __ldg(&Wm1[k * 128 + t]);
        const float4* r = (const float4*)&sCtx[k * 8];
        const float4 c0 = r[0], c1 = r[1];
        h2[0] += c0.x * w; h2[1] += c0.y * w; h2[2] += c0.z * w; h2[3] += c0.w * w;
        h2[4] += c1.x * w; h2[5] += c1.y * w; h2[6] += c1.z * w; h2[7] += c1.w * w;
    }
#pragma unroll
    for (int n = 0; n < 8; n++) sH2[t * 8 + n] = silu_f(h2[n]);
    __syncthreads();

    // y[n][m], m in {t, t+128, t+256}
    float ya[8], yb[8], yc[8];
    {
        const float c0 = __ldg(&bm2[t]);
        const float c1 = __ldg(&bm2[128 + t]);
        const float c2 = __ldg(&bm2[256 + t]);
#pragma unroll
        for (int n = 0; n < 8; n++) { ya[n] = c0; yb[n] = c1; yc[n] = c2; }
    }
#pragma unroll 2
    for (int k = 0; k < 128; k++) {
        const float w0 = __ldg(&Wm2[k * 384 + t]);
        const float w1 = __ldg(&Wm2[k * 384 + 128 + t]);
        const float w2 = __ldg(&Wm2[k * 384 + 256 + t]);
        const float4* r = (const float4*)&sH2[k * 8];
        const float4 h0 = r[0], h1 = r[1];
        ya[0] += h0.x * w0; ya[1] += h0.y * w0; ya[2] += h0.z * w0; ya[3] += h0.w * w0;
        ya[4] += h1.x * w0; ya[5] += h1.y * w0; ya[6] += h1.z * w0; ya[7] += h1.w * w0;
        yb[0] += h0.x * w1; yb[1] += h0.y * w1; yb[2] += h0.z * w1; yb[3] += h0.w * w1;
        yb[4] += h1.x * w1; yb[5] += h1.y * w1; yb[6] += h1.z * w1; yb[7] += h1.w * w1;
        yc[0] += h0.x * w2; yc[1] += h0.y * w2; yc[2] += h0.z * w2; yc[3] += h0.w * w2;
        yc[4] += h1.x * w2; yc[5] += h1.y * w2; yc[6] += h1.z * w2; yc[7] += h1.w * w2;
    }

    // outputs
#pragma unroll
    for (int n = 0; n < 8; n++) {
        out_q[(n0 + n) * 128 + t] = qn[n] + ya[n] + yc[n] * sdot[n];
#pragma unroll
        for (int v = 0; v < 3; v++)
            out_mu[(n0 + n) * 384 + v * 128 + t] =
                munr[v * 8 + n] + yb[n] * accW[v * 8 + n];
    }
}

// ============================================================================
extern "C" void kernel_launch(void* const* d_in, const int* in_sizes, int n_in,
                              void* d_out, int out_size)
{
    const float* q     = (const float*)d_in[0];
    const float* mu    = (const float*)d_in[1];
    const int*   eidx  = (const int*)d_in[2];
    const float* ew    = (const float*)d_in[3];
    const float* evers = (const float*)d_in[4];
    const float* eattr = (const float*)d_in[5];
    const float* Wf    = (const float*)d_in[6];
    const float* bf    = (const float*)d_in[7];
    const float* W1    = (const float*)d_in[8];
    const float* b1    = (const float*)d_in[9];
    const float* W2    = (const float*)d_in[10];
    const float* b2    = (const float*)d_in[11];
    const float* Wmix  = (const float*)d_in[12];
    const float* Wm1   = (const float*)d_in[13];
    const float* bm1   = (const float*)d_in[14];
    const float* Wm2   = (const float*)d_in[15];
    const float* bm2   = (const float*)d_in[16];

    float* out   = (float*)d_out;
    float* out_q = out;
    float* out_mu = out + (size_t)NN * 128;

    k_node_mlp<<<NN / 8, 128>>>(q, W1, b1, W2, b2);
    k_edge<<<EE / (8 * EPW), 256>>>(eidx, ew, evers, eattr, Wf, bf, mu);
    k_mix<<<NN / 8, 128>>>(q, mu, Wmix, Wm1, bm1, Wm2, bm2, out_q, out_mu);
}

// round 5
// speedup vs baseline: 1.1501x; 1.1501x over previous
#include <cuda_runtime.h>
#include <cuda_bf16.h>
#include <cstdint>

#define NN 20000
#define EE 320000
#define CC 128
#define BB 20
#define RCUT 5.0f
#define EPSN 1e-8f
#define PI_F 3.14159265358979323846f

typedef unsigned long long u64;

// ---------------- scratch (static device globals; no allocation) -------------
__device__ float g_x[NN * 384];     // x = silu(q@W1+b1)@W2+b2, [N,384]
__device__ float g_dq[NN * 128];    // scatter accum dq
__device__ float g_dmu[NN * 384];   // scatter accum dmu [N,3,128]

__device__ __forceinline__ float silu_f(float v) {
    return v / (1.0f + __expf(-v));
}

// ---- packed fp32x2 helpers (Blackwell FFMA2 via PTX) ----
__device__ __forceinline__ u64 pack2(float lo, float hi) {
    u64 r; asm("mov.b64 %0, {%1, %2};" : "=l"(r) : "f"(lo), "f"(hi)); return r;
}
__device__ __forceinline__ void unpack2(u64 p, float& lo, float& hi) {
    asm("mov.b64 {%0, %1}, %2;" : "=f"(lo), "=f"(hi) : "l"(p));
}
__device__ __forceinline__ u64 ffma2(u64 a, u64 b, u64 c) {
    u64 d; asm("fma.rn.f32x2 %0, %1, %2, %3;" : "=l"(d) : "l"(a), "l"(b), "l"(c));
    return d;
}

__device__ __forceinline__ void red_add_v4(float* ptr, float4 v) {
    asm volatile("red.global.add.v4.f32 [%0], {%1, %2, %3, %4};"
                 :: "l"(ptr), "f"(v.x), "f"(v.y), "f"(v.z), "f"(v.w)
                 : "memory");
}

// ============================================================================
// K1: per-node context MLP  x = silu(q@W1+b1)@W2+b2   (+ zero dq/dmu accums)
// block = 128 threads, 16 nodes per block, grid = N/16 = 1250
// ============================================================================
__global__ __launch_bounds__(128) void k_node_mlp(
    const float* __restrict__ q,
    const float* __restrict__ W1, const float* __restrict__ b1,
    const float* __restrict__ W2, const float* __restrict__ b2)
{
    __shared__ float sT[128 * 16];   // transposed activations [k][n]
    const int t = threadIdx.x;
    const int n0 = blockIdx.x * 16;

    // zero the scatter accumulators for this node range (before K2 runs)
#pragma unroll
    for (int n = 0; n < 16; n++) {
        g_dq[(n0 + n) * 128 + t] = 0.0f;
        g_dmu[(n0 + n) * 384 + t] = 0.0f;
        g_dmu[(n0 + n) * 384 + 128 + t] = 0.0f;
        g_dmu[(n0 + n) * 384 + 256 + t] = 0.0f;
    }

    // stage qT: sT[k=t][n]
#pragma unroll
    for (int n = 0; n < 16; n++) sT[t * 16 + n] = q[(n0 + n) * 128 + t];
    __syncthreads();

    // h[n][t] = silu(b1[t] + sum_k q[n][k] * W1[k][t])
    u64 acc[8];
    {
        const float bb = __ldg(&b1[t]);
        const u64 bb2 = pack2(bb, bb);
#pragma unroll
        for (int u = 0; u < 8; u++) acc[u] = bb2;
    }
#pragma unroll 4
    for (int k = 0; k < 128; k++) {
        const float w = __ldg(&W1[k * 128 + t]);
        const u64 w2 = pack2(w, w);
        const ulonglong2* r = (const ulonglong2*)&sT[k * 16];
        const ulonglong2 a0 = r[0], a1 = r[1], a2 = r[2], a3 = r[3];
        acc[0] = ffma2(a0.x, w2, acc[0]); acc[1] = ffma2(a0.y, w2, acc[1]);
        acc[2] = ffma2(a1.x, w2, acc[2]); acc[3] = ffma2(a1.y, w2, acc[3]);
        acc[4] = ffma2(a2.x, w2, acc[4]); acc[5] = ffma2(a2.y, w2, acc[5]);
        acc[6] = ffma2(a3.x, w2, acc[6]); acc[7] = ffma2(a3.y, w2, acc[7]);
    }
    __syncthreads();
#pragma unroll
    for (int u = 0; u < 8; u++) {
        float lo, hi; unpack2(acc[u], lo, hi);
        sT[t * 16 + 2 * u]     = silu_f(lo);
        sT[t * 16 + 2 * u + 1] = silu_f(hi);
    }
    __syncthreads();

    // x[n][m] for m in {t, t+128, t+256}
    u64 y0[8], y1[8], y2[8];
    {
        const float c0 = __ldg(&b2[t]);
        const float c1 = __ldg(&b2[128 + t]);
        const float c2 = __ldg(&b2[256 + t]);
        const u64 p0 = pack2(c0, c0), p1 = pack2(c1, c1), p2 = pack2(c2, c2);
#pragma unroll
        for (int u = 0; u < 8; u++) { y0[u] = p0; y1[u] = p1; y2[u] = p2; }
    }
#pragma unroll 2
    for (int k = 0; k < 128; k++) {
        const u64 w0 = pack2(__ldg(&W2[k * 384 + t]),       __ldg(&W2[k * 384 + t]));
        const u64 w1 = pack2(__ldg(&W2[k * 384 + 128 + t]), __ldg(&W2[k * 384 + 128 + t]));
        const u64 w2 = pack2(__ldg(&W2[k * 384 + 256 + t]), __ldg(&W2[k * 384 + 256 + t]));
        const ulonglong2* r = (const ulonglong2*)&sT[k * 16];
        const ulonglong2 h0 = r[0], h1 = r[1], h2 = r[2], h3 = r[3];
        y0[0] = ffma2(h0.x, w0, y0[0]); y0[1] = ffma2(h0.y, w0, y0[1]);
        y0[2] = ffma2(h1.x, w0, y0[2]); y0[3] = ffma2(h1.y, w0, y0[3]);
        y0[4] = ffma2(h2.x, w0, y0[4]); y0[5] = ffma2(h2.y, w0, y0[5]);
        y0[6] = ffma2(h3.x, w0, y0[6]); y0[7] = ffma2(h3.y, w0, y0[7]);
        y1[0] = ffma2(h0.x, w1, y1[0]); y1[1] = ffma2(h0.y, w1, y1[1]);
        y1[2] = ffma2(h1.x, w1, y1[2]); y1[3] = ffma2(h1.y, w1, y1[3]);
        y1[4] = ffma2(h2.x, w1, y1[4]); y1[5] = ffma2(h2.y, w1, y1[5]);
        y1[6] = ffma2(h3.x, w1, y1[6]); y1[7] = ffma2(h3.y, w1, y1[7]);
        y2[0] = ffma2(h0.x, w2, y2[0]); y2[1] = ffma2(h0.y, w2, y2[1]);
        y2[2] = ffma2(h1.x, w2, y2[2]); y2[3] = ffma2(h1.y, w2, y2[3]);
        y2[4] = ffma2(h2.x, w2, y2[4]); y2[5] = ffma2(h2.y, w2, y2[5]);
        y2[6] = ffma2(h3.x, w2, y2[6]); y2[7] = ffma2(h3.y, w2, y2[7]);
    }
#pragma unroll
    for (int u = 0; u < 8; u++) {
        float a, b;
        unpack2(y0[u], a, b);
        g_x[(n0 + 2 * u) * 384 + t] = a;       g_x[(n0 + 2 * u + 1) * 384 + t] = b;
        unpack2(y1[u], a, b);
        g_x[(n0 + 2 * u) * 384 + 128 + t] = a; g_x[(n0 + 2 * u + 1) * 384 + 128 + t] = b;
        unpack2(y2[u], a, b);
        g_x[(n0 + 2 * u) * 384 + 256 + t] = a; g_x[(n0 + 2 * u + 1) * 384 + 256 + t] = b;
    }
}

// ============================================================================
// K2: edge message kernel. warp per edge (16 edges/warp), 256 thr/block.
// ============================================================================
#define EPW 16
__global__ __launch_bounds__(256) void k_edge(
    const int*   __restrict__ eidx,     // [2,E]
    const float* __restrict__ ew,       // [E]
    const float* __restrict__ evers,    // [E,3]
    const float* __restrict__ eattr,    // [E,B]
    const float* __restrict__ Wf,       // [B,384]
    const float* __restrict__ bf,       // [384]
    const float* __restrict__ mu)       // [N,3,128]
{
    __shared__ float sWf[BB * 384];
    __shared__ float sBf[384];
    for (int i = threadIdx.x; i < BB * 384; i += 256) sWf[i] = Wf[i];
    for (int i = threadIdx.x; i < 384; i += 256) sBf[i] = bf[i];
    __syncthreads();

    const int warp = threadIdx.x >> 5;
    const int lane = threadIdx.x & 31;
    const int c0 = lane * 4;
    const int ebase = (blockIdx.x * 8 + warp) * EPW;

    const ulonglong2 bfa = *(const ulonglong2*)&sBf[c0];
    const ulonglong2 bfb = *(const ulonglong2*)&sBf[128 + c0];
    const ulonglong2 bfc = *(const ulonglong2*)&sBf[256 + c0];

    for (int it = 0; it < EPW; it++) {
        const int e = ebase + it;
        const int i = eidx[e];
        const int j = eidx[EE + e];
        const float wgt = __ldg(&ew[e]);
        const float fcut = (wgt < RCUT)
            ? 0.5f * (cosf((PI_F / RCUT) * wgt) + 1.0f) : 0.0f;
        const float a = (lane < BB) ? __ldg(&eattr[e * BB + lane]) : 0.0f;
        const float vx = __ldg(&evers[e * 3 + 0]);
        const float vy = __ldg(&evers[e * 3 + 1]);
        const float vz = __ldg(&evers[e * 3 + 2]);

        // filter GEMM row: 6 packed pairs covering this lane's 12 channels
        u64 p0 = bfa.x, p1 = bfa.y, p2 = bfb.x, p3 = bfb.y, p4 = bfc.x, p5 = bfc.y;
#pragma unroll
        for (int b = 0; b < BB; b++) {
            const float ab = __shfl_sync(0xffffffffu, a, b);
            const u64 ab2 = pack2(ab, ab);
            const ulonglong2 f0 = *(const ulonglong2*)&sWf[b * 384 + c0];
            const ulonglong2 f1 = *(const ulonglong2*)&sWf[b * 384 + 128 + c0];
            const ulonglong2 f2 = *(const ulonglong2*)&sWf[b * 384 + 256 + c0];
            p0 = ffma2(f0.x, ab2, p0); p1 = ffma2(f0.y, ab2, p1);
            p2 = ffma2(f1.x, ab2, p2); p3 = ffma2(f1.y, ab2, p3);
            p4 = ffma2(f2.x, ab2, p4); p5 = ffma2(f2.y, ab2, p5);
        }
        float4 w0, w1, w2;
        unpack2(p0, w0.x, w0.y); unpack2(p1, w0.z, w0.w);
        unpack2(p2, w1.x, w1.y); unpack2(p3, w1.z, w1.w);
        unpack2(p4, w2.x, w2.y); unpack2(p5, w2.z, w2.w);
        w0.x *= fcut; w0.y *= fcut; w0.z *= fcut; w0.w *= fcut;
        w1.x *= fcut; w1.y *= fcut; w1.z *= fcut; w1.w *= fcut;
        w2.x *= fcut; w2.y *= fcut; w2.z *= fcut; w2.w *= fcut;

        const float4 x0 = __ldg((const float4*)&g_x[j * 384 + c0]);
        const float4 x1 = __ldg((const float4*)&g_x[j * 384 + 128 + c0]);
        const float4 x2 = __ldg((const float4*)&g_x[j * 384 + 256 + c0]);

        float4 dq, dR, dM;
        dq.x = x0.x * w0.x; dq.y = x0.y * w0.y; dq.z = x0.z * w0.z; dq.w = x0.w * w0.w;
        dR.x = x1.x * w1.x; dR.y = x1.y * w1.y; dR.z = x1.z * w1.z; dR.w = x1.w * w1.w;
        dM.x = x2.x * w2.x; dM.y = x2.y * w2.y; dM.z = x2.z * w2.z; dM.w = x2.w * w2.w;

        const float4 m0 = __ldg((const float4*)&mu[j * 384 + c0]);
        const float4 m1 = __ldg((const float4*)&mu[j * 384 + 128 + c0]);
        const float4 m2 = __ldg((const float4*)&mu[j * 384 + 256 + c0]);

        float4 d0, d1, d2;
        d0.x = dR.x * vx + dM.x * m0.x; d0.y = dR.y * vx + dM.y * m0.y;
        d0.z = dR.z * vx + dM.z * m0.z; d0.w = dR.w * vx + dM.w * m0.w;
        d1.x = dR.x * vy + dM.x * m1.x; d1.y = dR.y * vy + dM.y * m1.y;
        d1.z = dR.z * vy + dM.z * m1.z; d1.w = dR.w * vy + dM.w * m1.w;
        d2.x = dR.x * vz + dM.x * m2.x; d2.y = dR.y * vz + dM.y * m2.y;
        d2.z = dR.z * vz + dM.z * m2.z; d2.w = dR.w * vz + dM.w * m2.w;

        red_add_v4(&g_dq[i * 128 + c0], dq);
        red_add_v4(&g_dmu[i * 384 + c0], d0);
        red_add_v4(&g_dmu[i * 384 + 128 + c0], d1);
        red_add_v4(&g_dmu[i * 384 + 256 + c0], d2);
    }
}

// ============================================================================
// K3: PaiNN mixing. block = 128 threads, 8 nodes per block, grid = 2500.
// accV/accW loops fused (one sMuT pass), mu_W spilled to smem for Wm2 phase.
// ============================================================================
__global__ __launch_bounds__(128) void k_mix(
    const float* __restrict__ q,
    const float* __restrict__ mu,
    const float* __restrict__ Wmix,   // [128,256]
    const float* __restrict__ Wm1,    // [256,128]
    const float* __restrict__ bm1,    // [128]
    const float* __restrict__ Wm2,    // [128,384]
    const float* __restrict__ bm2,    // [384]
    float* __restrict__ out_q,        // [N,128]
    float* __restrict__ out_mu)       // [N,3,128]
{
    __shared__ float sMuT[128 * 24];   // [k][v*8+n]  (mun transposed)
    __shared__ float sAW[128 * 24];    // stash of mu_W per (t-channel)[v*8+n]
    __shared__ float sCtx[256 * 8];    // [k][n]
    __shared__ float sH2[128 * 8];     // [k][n]
    const int t = threadIdx.x;
    const int n0 = blockIdx.x * 8;

    // mun = mu + dmu staged transposed in smem; qn = q + dq in regs
    float qn[8];
#pragma unroll
    for (int v = 0; v < 3; v++)
#pragma unroll
        for (int n = 0; n < 8; n++) {
            const int gi = (n0 + n) * 384 + v * 128 + t;
            sMuT[t * 24 + v * 8 + n] = mu[gi] + g_dmu[gi];
        }
#pragma unroll
    for (int n = 0; n < 8; n++)
        qn[n] = q[(n0 + n) * 128 + t] + g_dq[(n0 + n) * 128 + t];
    __syncthreads();

    // fused: mu_V and mu_W GEMMs over one sMuT pass
    u64 aV[12], aW[12];
#pragma unroll
    for (int u = 0; u < 12; u++) { aV[u] = 0ull; aW[u] = 0ull; }
#pragma unroll 2
    for (int k = 0; k < 128; k++) {
        const float wv = __ldg(&Wmix[k * 256 + t]);
        const float ww = __ldg(&Wmix[k * 256 + 128 + t]);
        const u64 wv2 = pack2(wv, wv);
        const u64 ww2 = pack2(ww, ww);
        const ulonglong2* r = (const ulonglong2*)&sMuT[k * 24];
#pragma unroll
        for (int u = 0; u < 6; u++) {
            const ulonglong2 m = r[u];
            aV[2 * u]     = ffma2(m.x, wv2, aV[2 * u]);
            aV[2 * u + 1] = ffma2(m.y, wv2, aV[2 * u + 1]);
            aW[2 * u]     = ffma2(m.x, ww2, aW[2 * u]);
            aW[2 * u + 1] = ffma2(m.y, ww2, aW[2 * u + 1]);
        }
    }
    float av[24], aw[24];
#pragma unroll
    for (int u = 0; u < 12; u++) {
        unpack2(aV[u], av[2 * u], av[2 * u + 1]);
        unpack2(aW[u], aw[2 * u], aw[2 * u + 1]);
    }

    float Vn[8], sdot[8];
#pragma unroll
    for (int n = 0; n < 8; n++) {
        Vn[n] = sqrtf(av[n] * av[n] + av[8 + n] * av[8 + n]
                      + av[16 + n] * av[16 + n] + EPSN);
        sdot[n] = av[n] * aw[n] + av[8 + n] * aw[8 + n] + av[16 + n] * aw[16 + n];
    }
    // stash mu_W in smem; free registers for the MLP phase
#pragma unroll
    for (int u = 0; u < 24; u++) sAW[t * 24 + u] = aw[u];

    // ctx = [qn, Vn] transposed
#pragma unroll
    for (int n = 0; n < 8; n++) {
        sCtx[t * 8 + n] = qn[n];
        sCtx[(128 + t) * 8 + n] = Vn[n];
    }
    __syncthreads();

    // h2[n][t] = silu(bm1[t] + sum_{k<256} ctx[n][k] * Wm1[k][t])
    u64 h[4];
    {
        const float bb = __ldg(&bm1[t]);
        const u64 bb2 = pack2(bb, bb);
#pragma unroll
        for (int u = 0; u < 4; u++) h[u] = bb2;
    }
#pragma unroll 4
    for (int k = 0; k < 256; k++) {
        const float w = __ldg(&Wm1[k * 128 + t]);
        const u64 w2 = pack2(w, w);
        const ulonglong2* r = (const ulonglong2*)&sCtx[k * 8];
        const ulonglong2 ca = r[0], cb = r[1];
        h[0] = ffma2(ca.x, w2, h[0]); h[1] = ffma2(ca.y, w2, h[1]);
        h[2] = ffma2(cb.x, w2, h[2]); h[3] = ffma2(cb.y, w2, h[3]);
    }
#pragma unroll
    for (int u = 0; u < 4; u++) {
        float lo, hi; unpack2(h[u], lo, hi);
        sH2[t * 8 + 2 * u]     = silu_f(lo);
        sH2[t * 8 + 2 * u + 1] = silu_f(hi);
    }
    __syncthreads();

    // y[n][m], m in {t, t+128, t+256}
    u64 ya[4], yb[4], yc[4];
    {
        const float c0 = __ldg(&bm2[t]);
        const float c1 = __ldg(&bm2[128 + t]);
        const float c2 = __ldg(&bm2[256 + t]);
        const u64 pa = pack2(c0, c0), pb = pack2(c1, c1), pc = pack2(c2, c2);
#pragma unroll
        for (int u = 0; u < 4; u++) { ya[u] = pa; yb[u] = pb; yc[u] = pc; }
    }
#pragma unroll 2
    for (int k = 0; k < 128; k++) {
        const float f0 = __ldg(&Wm2[k * 384 + t]);
        const float f1 = __ldg(&Wm2[k * 384 + 128 + t]);
        const float f2 = __ldg(&Wm2[k * 384 + 256 + t]);
        const u64 w0 = pack2(f0, f0), w1 = pack2(f1, f1), w2 = pack2(f2, f2);
        const ulonglong2* r = (const ulonglong2*)&sH2[k * 8];
        const ulonglong2 ha = r[0], hb = r[1];
        ya[0] = ffma2(ha.x, w0, ya[0]); ya[1] = ffma2(ha.y, w0, ya[1]);
        ya[2] = ffma2(hb.x, w0, ya[2]); ya[3] = ffma2(hb.y, w0, ya[3]);
        yb[0] = ffma2(ha.x, w1, yb[0]); yb[1] = ffma2(ha.y, w1, yb[1]);
        yb[2] = ffma2(hb.x, w1, yb[2]); yb[3] = ffma2(hb.y, w1, yb[3]);
        yc[0] = ffma2(ha.x, w2, yc[0]); yc[1] = ffma2(ha.y, w2, yc[1]);
        yc[2] = ffma2(hb.x, w2, yc[2]); yc[3] = ffma2(hb.y, w2, yc[3]);
    }
    float Ya[8], Yb[8], Yc[8];
#pragma unroll
    for (int u = 0; u < 4; u++) {
        unpack2(ya[u], Ya[2 * u], Ya[2 * u + 1]);
        unpack2(yb[u], Yb[2 * u], Yb[2 * u + 1]);
        unpack2(yc[u], Yc[2 * u], Yc[2 * u + 1]);
    }

    // outputs (sMuT / sAW rows are thread-private: no sync needed)
#pragma unroll
    for (int n = 0; n < 8; n++) {
        out_q[(n0 + n) * 128 + t] = qn[n] + Ya[n] + Yc[n] * sdot[n];
#pragma unroll
        for (int v = 0; v < 3; v++)
            out_mu[(n0 + n) * 384 + v * 128 + t] =
                sMuT[t * 24 + v * 8 + n] + Yb[n] * sAW[t * 24 + v * 8 + n];
    }
}

// ============================================================================
extern "C" void kernel_launch(void* const* d_in, const int* in_sizes, int n_in,
                              void* d_out, int out_size)
{
    const float* q     = (const float*)d_in[0];
    const float* mu    = (const float*)d_in[1];
    const int*   eidx  = (const int*)d_in[2];
    const float* ew    = (const float*)d_in[3];
    const float* evers = (const float*)d_in[4];
    const float* eattr = (const float*)d_in[5];
    const float* Wf    = (const float*)d_in[6];
    const float* bf    = (const float*)d_in[7];
    const float* W1    = (const float*)d_in[8];
    const float* b1    = (const float*)d_in[9];
    const float* W2    = (const float*)d_in[10];
    const float* b2    = (const float*)d_in[11];
    const float* Wmix  = (const float*)d_in[12];
    const float* Wm1   = (const float*)d_in[13];
    const float* bm1   = (const float*)d_in[14];
    const float* Wm2   = (const float*)d_in[15];
    const float* bm2   = (const float*)d_in[16];

    float* out   = (float*)d_out;
    float* out_q = out;
    float* out_mu = out + (size_t)NN * 128;

    k_node_mlp<<<NN / 16, 128>>>(q, W1, b1, W2, b2);
    k_edge<<<EE / (8 * EPW), 256>>>(eidx, ew, evers, eattr, Wf, bf, mu);
    k_mix<<<NN / 8, 128>>>(q, mu, Wmix, Wm1, bm1, Wm2, bm2, out_q, out_mu);
}